// round 11
// baseline (speedup 1.0000x reference)
#include <cuda_runtime.h>
#include <cstdint>

// minGRU bidirectional scan. R11: 2-CTA cluster per sequence — each CTA owns
// half (4096 elems), rank0 passes the mid-state scalar to rank1 via DSMEM.
// x: [B, 512, L] fp32 -> out: [B, 256, L] fp32.
//   cluster cid = blockIdx.x/2 -> b = cid>>8, c2 = cid&255; rev = c2>=128.
//   h row = x[b, (rev?256:0)+(c2&127), :], gate row = +128 channels.
// Recurrence (logical order; rev scans t = L-1..0):
//   out_t = a_t*out_{t-1} + b_t,  a = 1/(1+e^gate), b = (1-a)*g(h),
//   g(v) = v>=0 ? 1+v : e^v.
//
// Rank r owns logical elems [r*HL, (r+1)*HL). Physical region for rev is the
// mirror; smem holds the region in physical order, local logical e' maps to
// smem elem (rev ? HL-1-e' : e'). Thread t owns 2 chunks of 4 (one per local
// half q): local float4 f = q*QF + t  -> smem float4 (rev ? F4H-1-f : f).

constexpr int L   = 8192;
constexpr int HL  = 4096;          // elements per CTA
constexpr int NT  = 512;
constexpr int NW  = NT / 32;       // 16 warps
constexpr int F4H = HL / 4;        // 1024 float4s per CTA
constexpr int QF  = F4H / 2;       // 512 float4s per local half
constexpr int HB  = HL * 4;        // 16384 bytes per row region

constexpr int SMEM_BYTES = 2 * HL * 4;   // dynamic: hbuf + gbuf

__device__ __forceinline__ float fast_rcp(float v) {
    float r;
    asm("rcp.approx.f32 %0, %1;" : "=f"(r) : "f"(v));
    return r;
}

__device__ __forceinline__ void mbar_wait_p0(uint32_t mbar) {
    uint32_t done;
    asm volatile(
        "{\n\t.reg .pred p;\n\t"
        "mbarrier.try_wait.parity.shared::cta.b64 p, [%1], 0;\n\t"
        "selp.b32 %0, 1, 0, p;\n\t}"
        : "=r"(done) : "r"(mbar) : "memory");
    while (!done) {
        asm volatile(
            "{\n\t.reg .pred p;\n\t"
            "mbarrier.try_wait.parity.shared::cta.b64 p, [%1], 0, 0x989680;\n\t"
            "selp.b32 %0, 1, 0, p;\n\t}"
            : "=r"(done) : "r"(mbar) : "memory");
    }
}

// acquire at cluster scope (pairs with remote release-arrive)
__device__ __forceinline__ void mbar_wait_p0_cluster(uint32_t mbar) {
    uint32_t done;
    asm volatile(
        "{\n\t.reg .pred p;\n\t"
        "mbarrier.try_wait.parity.acquire.cluster.shared::cta.b64 p, [%1], 0;\n\t"
        "selp.b32 %0, 1, 0, p;\n\t}"
        : "=r"(done) : "r"(mbar) : "memory");
    while (!done) {
        asm volatile(
            "{\n\t.reg .pred p;\n\t"
            "mbarrier.try_wait.parity.acquire.cluster.shared::cta.b64 p, [%1], 0, 0x989680;\n\t"
            "selp.b32 %0, 1, 0, p;\n\t}"
            : "=r"(done) : "r"(mbar) : "memory");
    }
}

__global__ __launch_bounds__(NT, 3) __cluster_dims__(2, 1, 1)
void mingru_bidir_kernel(const float* __restrict__ x, float* __restrict__ out) {
    extern __shared__ float smem[];
    float* hbuf = smem;
    float* gbuf = smem + HL;
    __shared__ float sA[2][NW], sB[2][NW], sT[4], sSeed;
    __shared__ uint64_t mbTma, mbSeed;

    uint32_t rank;
    asm("mov.u32 %0, %%cluster_ctarank;" : "=r"(rank));

    const int cid = blockIdx.x >> 1;
    const int b   = cid >> 8;
    const int c2  = cid & 255;
    const bool rev = (c2 & 128) != 0;
    const int hch = ((c2 & 128) ? 256 : 0) + (c2 & 127);

    const float* hrow = x + (size_t)(b * 512 + hch) * L;
    const float* grow = hrow + (size_t)128 * L;
    float4* __restrict__ o4 = (float4*)(out + (size_t)(b * 256 + c2) * L);

    const int tid  = threadIdx.x;
    const int lane = tid & 31;
    const int warp = tid >> 5;

    // physical region this CTA stages: logical [rank*HL,(rank+1)*HL)
    const int regstart = rev ? (L - ((int)rank + 1) * HL) : (int)rank * HL;

    const uint32_t hbuf_u32 = (uint32_t)__cvta_generic_to_shared(hbuf);
    const uint32_t gbuf_u32 = (uint32_t)__cvta_generic_to_shared(gbuf);
    const uint32_t mbT_u32  = (uint32_t)__cvta_generic_to_shared(&mbTma);
    const uint32_t mbS_u32  = (uint32_t)__cvta_generic_to_shared(&mbSeed);
    const uint32_t seed_u32 = (uint32_t)__cvta_generic_to_shared(&sSeed);

    if (tid == 0) {
        asm volatile("mbarrier.init.shared.b64 [%0], 1;" :: "r"(mbT_u32) : "memory");
        asm volatile("mbarrier.init.shared.b64 [%0], 1;" :: "r"(mbS_u32) : "memory");
        asm volatile("mbarrier.arrive.expect_tx.shared.b64 _, [%0], %1;"
                     :: "r"(mbT_u32), "r"(2 * HB) : "memory");
        asm volatile("cp.async.bulk.shared::cta.global.mbarrier::complete_tx::bytes "
                     "[%0], [%1], %2, [%3];"
                     :: "r"(hbuf_u32), "l"(hrow + regstart), "r"(HB), "r"(mbT_u32) : "memory");
        asm volatile("cp.async.bulk.shared::cta.global.mbarrier::complete_tx::bytes "
                     "[%0], [%1], %2, [%3];"
                     :: "r"(gbuf_u32), "l"(grow + regstart), "r"(HB), "r"(mbT_u32) : "memory");
    }
    __syncthreads();
    // both CTAs' mbSeed inits must be visible before rank0's remote arrive
    asm volatile("barrier.cluster.arrive.aligned;" ::: "memory");
    asm volatile("barrier.cluster.wait.aligned;" ::: "memory");

    mbar_wait_p0(mbT_u32);

    const float4* h4 = (const float4*)hbuf;
    const float4* g4 = (const float4*)gbuf;

    int sidx[2];
    #pragma unroll
    for (int q = 0; q < 2; ++q) {
        const int f = q * QF + tid;
        sidx[q] = rev ? (F4H - 1 - f) : f;
    }

    // ---- Phase 1: vector gather + pointwise + per-half compose ----
    float av[8], bv[8];
    float Aq[2], Bq[2];
    #pragma unroll
    for (int q = 0; q < 2; ++q) {
        float4 hv = h4[sidx[q]];
        float4 gv = g4[sidx[q]];
        if (rev) {
            hv = make_float4(hv.w, hv.z, hv.y, hv.x);
            gv = make_float4(gv.w, gv.z, gv.y, gv.x);
        }
        const float hh[4] = {hv.x, hv.y, hv.z, hv.w};
        const float gg[4] = {gv.x, gv.y, gv.z, gv.w};
        float A = 1.0f, B = 0.0f;
        #pragma unroll
        for (int k = 0; k < 4; ++k) {
            const int j = q * 4 + k;
            const float a  = fast_rcp(1.0f + __expf(gg[k]));
            const float gh = (hh[k] >= 0.0f) ? (1.0f + hh[k]) : __expf(hh[k]);
            const float bb = (1.0f - a) * gh;
            av[j] = a;
            bv[j] = bb;
            B = fmaf(B, a, bb);
            A *= a;
        }
        Aq[q] = A;
        Bq[q] = B;
    }

    // ---- Phase 2: 2 interleaved warp scans ----
    #pragma unroll
    for (int off = 1; off < 32; off <<= 1) {
        #pragma unroll
        for (int q = 0; q < 2; ++q) {
            const float Au = __shfl_up_sync(0xFFFFFFFFu, Aq[q], off);
            const float Bu = __shfl_up_sync(0xFFFFFFFFu, Bq[q], off);
            if (lane >= off) {
                Bq[q] = fmaf(Bu, Aq[q], Bq[q]);
                Aq[q] *= Au;
            }
        }
    }
    float Ae[2], Be[2];
    #pragma unroll
    for (int q = 0; q < 2; ++q) {
        Ae[q] = __shfl_up_sync(0xFFFFFFFFu, Aq[q], 1);
        Be[q] = __shfl_up_sync(0xFFFFFFFFu, Bq[q], 1);
        if (lane == 0) { Ae[q] = 1.0f; Be[q] = 0.0f; }
        if (lane == 31) { sA[q][warp] = Aq[q]; sB[q][warp] = Bq[q]; }
    }
    __syncthreads();

    // ---- warp0: block scan over warp totals; rank0 ships mid-state ----
    if (warp == 0) {
        float wa[2], wb[2];
        #pragma unroll
        for (int q = 0; q < 2; ++q) {
            wa[q] = sA[q][lane & (NW - 1)];
            wb[q] = sB[q][lane & (NW - 1)];
        }
        #pragma unroll
        for (int off = 1; off < NW; off <<= 1) {
            #pragma unroll
            for (int q = 0; q < 2; ++q) {
                const float Au = __shfl_up_sync(0xFFFFFFFFu, wa[q], off);
                const float Bu = __shfl_up_sync(0xFFFFFFFFu, wb[q], off);
                if (lane >= off) {
                    wb[q] = fmaf(Bu, wa[q], wb[q]);
                    wa[q] *= Au;
                }
            }
        }
        // inclusive CTA totals live at lane NW-1; mid-state = (T1 o T0)(0)
        const float smid_send = fmaf(wa[1], wb[0], wb[1]);
        #pragma unroll
        for (int q = 0; q < 2; ++q) {
            const float wae = __shfl_up_sync(0xFFFFFFFFu, wa[q], 1);   // full warp
            const float wbe = __shfl_up_sync(0xFFFFFFFFu, wb[q], 1);   // full warp
            if (lane < NW) {
                sA[q][lane] = (lane == 0) ? 1.0f : wae;
                sB[q][lane] = (lane == 0) ? 0.0f : wbe;
            }
            if (lane == NW - 1) { sT[2 * q] = wa[q]; sT[2 * q + 1] = wb[q]; }
        }
        if (lane == NW - 1 && rank == 0) {
            uint32_t remSeed, remBar;
            asm("mapa.shared::cluster.u32 %0, %1, 1;" : "=r"(remSeed) : "r"(seed_u32));
            asm("mapa.shared::cluster.u32 %0, %1, 1;" : "=r"(remBar)  : "r"(mbS_u32));
            asm volatile("st.shared::cluster.f32 [%0], %1;"
                         :: "r"(remSeed), "f"(smid_send) : "memory");
            asm volatile("mbarrier.arrive.release.cluster.shared::cluster.b64 _, [%0];"
                         :: "r"(remBar) : "memory");
        }
    }
    __syncthreads();

    // rank1 seeds with the state after rank0's half; rank0 seeds with 0
    float ctaSeed = 0.0f;
    if (rank == 1) {
        mbar_wait_p0_cluster(mbS_u32);
        ctaSeed = sSeed;
    }

    float seed[2];
    seed[0] = ctaSeed;
    seed[1] = fmaf(sT[0], ctaSeed, sT[1]);   // state after local half 0

    // ---- Phase 3: replay + direct coalesced STG.128 ----
    #pragma unroll
    for (int q = 0; q < 2; ++q) {
        float s = fmaf(Ae[q], fmaf(sA[q][warp], seed[q], sB[q][warp]), Be[q]);
        float o[4];
        #pragma unroll
        for (int k = 0; k < 4; ++k) {
            s = fmaf(av[q * 4 + k], s, bv[q * 4 + k]);
            o[k] = s;
        }
        const int gf   = (int)rank * F4H + q * QF + tid;   // logical global float4
        const int gidx = rev ? (L / 4 - 1 - gf) : gf;      // physical float4
        o4[gidx] = rev ? make_float4(o[3], o[2], o[1], o[0])
                       : make_float4(o[0], o[1], o[2], o[3]);
    }
}

extern "C" void kernel_launch(void* const* d_in, const int* in_sizes, int n_in,
                              void* d_out, int out_size) {
    const float* x = (const float*)d_in[0];
    float* out = (float*)d_out;
    const int B = in_sizes[0] / (512 * L);
    cudaFuncSetAttribute(mingru_bidir_kernel,
                         cudaFuncAttributeMaxDynamicSharedMemorySize, SMEM_BYTES);
    mingru_bidir_kernel<<<B * 256 * 2, NT, SMEM_BYTES>>>(x, out);
}

// round 12
// speedup vs baseline: 1.1263x; 1.1263x over previous
#include <cuda_runtime.h>
#include <cstdint>

// minGRU bidirectional scan. R12: half-sequence CTAs, decoupled handoff via
// global memory (no clusters). Blocks [0,nseq) = first-half producers,
// [nseq,2nseq) = second-half consumers. Producer publishes the mid-state
// scalar as a packed {flag,value} 64-bit word (st.release.gpu); consumer
// polls with ld.acquire.gpu AFTER its own scan, then resets the word to 0
// so the __device__ scratch is zero for every graph replay.
// x: [B, 512, L] fp32 -> out: [B, 256, L] fp32.
//   seq (0..255 per batch): rev = seq&128; h row = x[b,(rev?256:0)+(seq&127),:],
//   gate row = +128 channels. Recurrence (logical order; rev scans t=L-1..0):
//   out_t = a_t*out_{t-1} + b_t,  a = 1/(1+e^gate), b = (1-a)*g(h),
//   g(v) = v>=0 ? 1+v : e^v.

constexpr int L   = 8192;
constexpr int HL  = 4096;        // elements per CTA (half sequence)
constexpr int NT  = 512;
constexpr int NW  = NT / 32;     // 16 warps
constexpr int F4H = HL / 4;      // 1024 float4s per half-region
constexpr int QF  = F4H / 2;     // 512 float4s per local quarter
constexpr int HB  = HL * 4;      // 16 KB per row region

constexpr int SMEM_BYTES = 2 * HL * 4;   // hbuf + gbuf = 32 KB

// zero-initialized; hi 32 bits = flag, lo 32 bits = mid-state float bits
__device__ unsigned long long g_sync[4096];

__device__ __forceinline__ float fast_rcp(float v) {
    float r;
    asm("rcp.approx.f32 %0, %1;" : "=f"(r) : "f"(v));
    return r;
}

__device__ __forceinline__ void mbar_wait_p0(uint32_t mbar) {
    uint32_t done;
    asm volatile(
        "{\n\t.reg .pred p;\n\t"
        "mbarrier.try_wait.parity.shared::cta.b64 p, [%1], 0;\n\t"
        "selp.b32 %0, 1, 0, p;\n\t}"
        : "=r"(done) : "r"(mbar) : "memory");
    while (!done) {
        asm volatile(
            "{\n\t.reg .pred p;\n\t"
            "mbarrier.try_wait.parity.shared::cta.b64 p, [%1], 0, 0x989680;\n\t"
            "selp.b32 %0, 1, 0, p;\n\t}"
            : "=r"(done) : "r"(mbar) : "memory");
    }
}

__global__ __launch_bounds__(NT, 3)
void mingru_bidir_kernel(const float* __restrict__ x, float* __restrict__ out) {
    extern __shared__ float smem[];
    float* hbuf = smem;
    float* gbuf = smem + HL;
    __shared__ float sA[2][NW], sB[2][NW], sT[2], sSeed;
    __shared__ uint64_t mbTma;

    const int nseq = gridDim.x >> 1;
    const int half = (blockIdx.x >= nseq) ? 1 : 0;   // 0=producer, 1=consumer
    const int seq  = blockIdx.x - half * nseq;

    const int b   = seq >> 8;
    const int c2  = seq & 255;
    const bool rev = (c2 & 128) != 0;
    const int hch = ((c2 & 128) ? 256 : 0) + (c2 & 127);

    const float* hrow = x + (size_t)(b * 512 + hch) * L;
    const float* grow = hrow + (size_t)128 * L;
    float4* __restrict__ o4 = (float4*)(out + (size_t)(b * 256 + c2) * L);

    const int tid  = threadIdx.x;
    const int lane = tid & 31;
    const int warp = tid >> 5;

    // this CTA's logical range [lo, lo+HL); physical region start:
    const int lo = half * HL;
    const int regstart = rev ? (L - lo - HL) : lo;

    const uint32_t hbuf_u32 = (uint32_t)__cvta_generic_to_shared(hbuf);
    const uint32_t gbuf_u32 = (uint32_t)__cvta_generic_to_shared(gbuf);
    const uint32_t mbT_u32  = (uint32_t)__cvta_generic_to_shared(&mbTma);

    if (tid == 0) {
        asm volatile("mbarrier.init.shared.b64 [%0], 1;" :: "r"(mbT_u32) : "memory");
        asm volatile("mbarrier.arrive.expect_tx.shared.b64 _, [%0], %1;"
                     :: "r"(mbT_u32), "r"(2 * HB) : "memory");
        asm volatile("cp.async.bulk.shared::cta.global.mbarrier::complete_tx::bytes "
                     "[%0], [%1], %2, [%3];"
                     :: "r"(hbuf_u32), "l"(hrow + regstart), "r"(HB), "r"(mbT_u32) : "memory");
        asm volatile("cp.async.bulk.shared::cta.global.mbarrier::complete_tx::bytes "
                     "[%0], [%1], %2, [%3];"
                     :: "r"(gbuf_u32), "l"(grow + regstart), "r"(HB), "r"(mbT_u32) : "memory");
    }
    __syncthreads();
    mbar_wait_p0(mbT_u32);

    const float4* h4 = (const float4*)hbuf;
    const float4* g4 = (const float4*)gbuf;

    // local logical float4 f = q*QF + tid -> physical smem f4
    int sidx[2];
    #pragma unroll
    for (int q = 0; q < 2; ++q) {
        const int f = q * QF + tid;
        sidx[q] = rev ? (F4H - 1 - f) : f;
    }

    // ---- Phase 1: conflict-free vector gather + pointwise + compose ----
    float av[8], bv[8];
    float Aq[2], Bq[2];
    #pragma unroll
    for (int q = 0; q < 2; ++q) {
        float4 hv = h4[sidx[q]];
        float4 gv = g4[sidx[q]];
        if (rev) {
            hv = make_float4(hv.w, hv.z, hv.y, hv.x);
            gv = make_float4(gv.w, gv.z, gv.y, gv.x);
        }
        const float hh[4] = {hv.x, hv.y, hv.z, hv.w};
        const float gg[4] = {gv.x, gv.y, gv.z, gv.w};
        float A = 1.0f, B = 0.0f;
        #pragma unroll
        for (int k = 0; k < 4; ++k) {
            const int j = q * 4 + k;
            const float a  = fast_rcp(1.0f + __expf(gg[k]));
            const float gh = (hh[k] >= 0.0f) ? (1.0f + hh[k]) : __expf(hh[k]);
            const float bb = (1.0f - a) * gh;
            av[j] = a;
            bv[j] = bb;
            B = fmaf(B, a, bb);
            A *= a;
        }
        Aq[q] = A;
        Bq[q] = B;
    }

    // ---- Phase 2: 2 interleaved warp scans ----
    #pragma unroll
    for (int off = 1; off < 32; off <<= 1) {
        #pragma unroll
        for (int q = 0; q < 2; ++q) {
            const float Au = __shfl_up_sync(0xFFFFFFFFu, Aq[q], off);
            const float Bu = __shfl_up_sync(0xFFFFFFFFu, Bq[q], off);
            if (lane >= off) {
                Bq[q] = fmaf(Bu, Aq[q], Bq[q]);
                Aq[q] *= Au;
            }
        }
    }
    float Ae[2], Be[2];
    #pragma unroll
    for (int q = 0; q < 2; ++q) {
        Ae[q] = __shfl_up_sync(0xFFFFFFFFu, Aq[q], 1);
        Be[q] = __shfl_up_sync(0xFFFFFFFFu, Bq[q], 1);
        if (lane == 0) { Ae[q] = 1.0f; Be[q] = 0.0f; }
        if (lane == 31) { sA[q][warp] = Aq[q]; sB[q][warp] = Bq[q]; }
    }
    __syncthreads();

    // ---- warp0: block scan over warp totals; producer publishes mid ----
    if (warp == 0) {
        float wa[2], wb[2];
        #pragma unroll
        for (int q = 0; q < 2; ++q) {
            wa[q] = sA[q][lane & (NW - 1)];
            wb[q] = sB[q][lane & (NW - 1)];
        }
        #pragma unroll
        for (int off = 1; off < NW; off <<= 1) {
            #pragma unroll
            for (int q = 0; q < 2; ++q) {
                const float Au = __shfl_up_sync(0xFFFFFFFFu, wa[q], off);
                const float Bu = __shfl_up_sync(0xFFFFFFFFu, wb[q], off);
                if (lane >= off) {
                    wb[q] = fmaf(Bu, wa[q], wb[q]);
                    wa[q] *= Au;
                }
            }
        }
        if (lane == NW - 1) {
            if (half == 0) {
                // mid-state = (T1 o T0)(0) over this CTA's 4096 elems
                const float mid = fmaf(wa[1], wb[0], wb[1]);
                const unsigned long long pk =
                    (1ull << 32) | (unsigned long long)__float_as_uint(mid);
                asm volatile("st.release.gpu.global.b64 [%0], %1;"
                             :: "l"(g_sync + seq), "l"(pk) : "memory");
            }
            sT[0] = wa[0];   // inclusive total of local quarter 0 (A)
            sT[1] = wb[0];   // (B)
        }
        #pragma unroll
        for (int q = 0; q < 2; ++q) {
            const float wae = __shfl_up_sync(0xFFFFFFFFu, wa[q], 1);   // full warp
            const float wbe = __shfl_up_sync(0xFFFFFFFFu, wb[q], 1);   // full warp
            if (lane < NW) {
                sA[q][lane] = (lane == 0) ? 1.0f : wae;
                sB[q][lane] = (lane == 0) ? 0.0f : wbe;
            }
        }
    }
    __syncthreads();

    // ---- consumer: acquire mid-state (published ~waves earlier), reset ----
    float ctaSeed = 0.0f;
    if (half) {
        if (tid == 0) {
            unsigned long long v;
            do {
                asm volatile("ld.acquire.gpu.global.b64 %0, [%1];"
                             : "=l"(v) : "l"(g_sync + seq) : "memory");
            } while ((v >> 32) == 0ull);
            sSeed = __uint_as_float((unsigned)(v & 0xFFFFFFFFull));
            asm volatile("st.relaxed.gpu.global.b64 [%0], %1;"
                         :: "l"(g_sync + seq), "l"(0ull) : "memory");
        }
        __syncthreads();            // uniform within consumer CTAs
        ctaSeed = sSeed;
    }

    float seed[2];
    seed[0] = ctaSeed;
    seed[1] = fmaf(sT[0], ctaSeed, sT[1]);   // state after local quarter 0

    // ---- Phase 3: replay + direct coalesced STG.128 ----
    #pragma unroll
    for (int q = 0; q < 2; ++q) {
        float s = fmaf(Ae[q], fmaf(sA[q][warp], seed[q], sB[q][warp]), Be[q]);
        float o[4];
        #pragma unroll
        for (int k = 0; k < 4; ++k) {
            s = fmaf(av[q * 4 + k], s, bv[q * 4 + k]);
            o[k] = s;
        }
        const int gf   = (lo >> 2) + q * QF + tid;       // logical global float4
        const int gidx = rev ? (L / 4 - 1 - gf) : gf;    // physical float4
        o4[gidx] = rev ? make_float4(o[3], o[2], o[1], o[0])
                       : make_float4(o[0], o[1], o[2], o[3]);
    }
}

extern "C" void kernel_launch(void* const* d_in, const int* in_sizes, int n_in,
                              void* d_out, int out_size) {
    const float* x = (const float*)d_in[0];
    float* out = (float*)d_out;
    const int B = in_sizes[0] / (512 * L);
    const int nseq = B * 256;   // <= 4096 (g_sync capacity)
    cudaFuncSetAttribute(mingru_bidir_kernel,
                         cudaFuncAttributeMaxDynamicSharedMemorySize, SMEM_BYTES);
    mingru_bidir_kernel<<<nseq * 2, NT, SMEM_BYTES>>>(x, out);
}

// round 13
// speedup vs baseline: 1.4118x; 1.2535x over previous
#include <cuda_runtime.h>
#include <cstdint>

// minGRU bidirectional scan. R13: intra-CTA chunk pipeline.
// One CTA per sequence (grid 2048). The 8192-elem sequence is processed as
// 4 chunks of 2048: per chunk = TMA-arrival wait -> pointwise -> block scan
// (1 barrier, redundant per-warp scan of warp totals) -> replay -> STG.
// Stores are spread across the CTA lifetime instead of bunched at the tail;
// loads drain chunk-by-chunk ahead of compute (all issued up front).
// x: [B, 512, L] fp32 -> out: [B, 256, L] fp32.
//   out channel c2 (0..255): rev = c2>=128; h row = x[b,(rev?256:0)+(c2&127),:],
//   gate row = +128 channels. Recurrence (logical order; rev scans t=L-1..0):
//   out_t = a_t*out_{t-1} + b_t,  a = 1/(1+e^gate), b = (1-a)*g(h),
//   g(v) = v>=0 ? 1+v : e^v.

constexpr int L  = 8192;
constexpr int NT = 512;
constexpr int NW = NT / 32;    // 16 warps
constexpr int CF = 512;        // float4s per chunk
constexpr int CE = 2048;       // elements per chunk
constexpr int CB = CE * 4;     // bytes per chunk row = 8192

constexpr int SMEM_BYTES = 2 * L * 4 + 4 * 8;   // hbuf | gbuf | mbar[4]

__device__ __forceinline__ float fast_rcp(float v) {
    float r;
    asm("rcp.approx.f32 %0, %1;" : "=f"(r) : "f"(v));
    return r;
}

__device__ __forceinline__ void mbar_wait_p0(uint32_t mbar) {
    uint32_t done;
    asm volatile(
        "{\n\t.reg .pred p;\n\t"
        "mbarrier.try_wait.parity.shared::cta.b64 p, [%1], 0;\n\t"
        "selp.b32 %0, 1, 0, p;\n\t}"
        : "=r"(done) : "r"(mbar) : "memory");
    while (!done) {
        asm volatile(
            "{\n\t.reg .pred p;\n\t"
            "mbarrier.try_wait.parity.shared::cta.b64 p, [%1], 0, 0x989680;\n\t"
            "selp.b32 %0, 1, 0, p;\n\t}"
            : "=r"(done) : "r"(mbar) : "memory");
    }
}

__global__ __launch_bounds__(NT, 3)
void mingru_bidir_kernel(const float* __restrict__ x, float* __restrict__ out) {
    extern __shared__ float smem[];
    float* hbuf = smem;
    float* gbuf = smem + L;
    uint64_t* mbar64 = (uint64_t*)(smem + 2 * L);

    __shared__ float sA[2][NW], sB[2][NW];   // double-buffered warp totals

    const int blk = blockIdx.x;
    const int b   = blk >> 8;
    const int c2  = blk & 255;
    const bool rev = (c2 & 128) != 0;
    const int hch = ((c2 & 128) ? 256 : 0) + (c2 & 127);

    const float* hrow = x + (size_t)(b * 512 + hch) * L;
    const float* grow = hrow + (size_t)128 * L;
    float4* __restrict__ o4 = (float4*)(out + (size_t)(b * 256 + c2) * L);

    const int tid  = threadIdx.x;
    const int lane = tid & 31;
    const int warp = tid >> 5;

    const uint32_t mbar_u32 = (uint32_t)__cvta_generic_to_shared(mbar64);
    const uint32_t hbuf_u32 = (uint32_t)__cvta_generic_to_shared(hbuf);
    const uint32_t gbuf_u32 = (uint32_t)__cvta_generic_to_shared(gbuf);

    // ---- issue 4 chunk loads, first-needed physical chunk first ----
    if (tid == 0) {
        #pragma unroll
        for (int i = 0; i < 4; ++i) {
            const int p = rev ? (3 - i) : i;
            asm volatile("mbarrier.init.shared.b64 [%0], 1;"
                         :: "r"(mbar_u32 + 8 * p) : "memory");
            asm volatile("mbarrier.arrive.expect_tx.shared.b64 _, [%0], %1;"
                         :: "r"(mbar_u32 + 8 * p), "r"(2 * CB) : "memory");
            asm volatile("cp.async.bulk.shared::cta.global.mbarrier::complete_tx::bytes "
                         "[%0], [%1], %2, [%3];"
                         :: "r"(hbuf_u32 + p * CB), "l"(hrow + p * CE),
                            "r"(CB), "r"(mbar_u32 + 8 * p) : "memory");
            asm volatile("cp.async.bulk.shared::cta.global.mbarrier::complete_tx::bytes "
                         "[%0], [%1], %2, [%3];"
                         :: "r"(gbuf_u32 + p * CB), "l"(grow + p * CE),
                            "r"(CB), "r"(mbar_u32 + 8 * p) : "memory");
        }
    }
    __syncthreads();   // mbarrier inits visible before any try_wait

    const float4* h4 = (const float4*)hbuf;
    const float4* g4 = (const float4*)gbuf;

    float carry = 0.0f;   // sequence state entering current chunk (all threads)

    #pragma unroll
    for (int c = 0; c < 4; ++c) {
        const int p = rev ? (3 - c) : c;          // physical chunk
        const int buf = c & 1;

        mbar_wait_p0(mbar_u32 + 8 * p);

        // logical f4 within sequence = c*CF + tid -> physical f4 index
        const int f    = c * CF + tid;
        const int fidx = rev ? (L / 4 - 1 - f) : f;

        // ---- pointwise + thread compose (4 elems) ----
        float4 hv = h4[fidx];
        float4 gv = g4[fidx];
        if (rev) {
            hv = make_float4(hv.w, hv.z, hv.y, hv.x);
            gv = make_float4(gv.w, gv.z, gv.y, gv.x);
        }
        const float hh[4] = {hv.x, hv.y, hv.z, hv.w};
        const float gg[4] = {gv.x, gv.y, gv.z, gv.w};
        float av[4], bv[4];
        float A = 1.0f, B = 0.0f;
        #pragma unroll
        for (int k = 0; k < 4; ++k) {
            const float a  = fast_rcp(1.0f + __expf(gg[k]));
            const float gh = (hh[k] >= 0.0f) ? (1.0f + hh[k]) : __expf(hh[k]);
            const float bb = (1.0f - a) * gh;
            av[k] = a;
            bv[k] = bb;
            B = fmaf(B, a, bb);
            A *= a;
        }

        // ---- warp inclusive scan ----
        #pragma unroll
        for (int off = 1; off < 32; off <<= 1) {
            const float Au = __shfl_up_sync(0xFFFFFFFFu, A, off);
            const float Bu = __shfl_up_sync(0xFFFFFFFFu, B, off);
            if (lane >= off) {
                B = fmaf(Bu, A, B);
                A *= Au;
            }
        }
        float Ae = __shfl_up_sync(0xFFFFFFFFu, A, 1);
        float Be = __shfl_up_sync(0xFFFFFFFFu, B, 1);
        if (lane == 0) { Ae = 1.0f; Be = 0.0f; }

        if (lane == 31) { sA[buf][warp] = A; sB[buf][warp] = B; }
        __syncthreads();   // single barrier per chunk (totals double-buffered)

        // ---- redundant block scan: every warp scans the 16 warp totals ----
        float wa = sA[buf][lane & (NW - 1)];
        float wb = sB[buf][lane & (NW - 1)];
        #pragma unroll
        for (int off = 1; off < NW; off <<= 1) {
            const float Au = __shfl_up_sync(0xFFFFFFFFu, wa, off);
            const float Bu = __shfl_up_sync(0xFFFFFFFFu, wb, off);
            if (lane >= off) {
                wb = fmaf(Bu, wa, wb);
                wa *= Au;
            }
        }
        // exclusive prefix for THIS warp = inclusive at lane (warp-1); identity for warp 0
        const int src = (warp == 0) ? 0 : (warp - 1);
        float prevA = __shfl_sync(0xFFFFFFFFu, wa, src);
        float prevB = __shfl_sync(0xFFFFFFFFu, wb, src);
        if (warp == 0) { prevA = 1.0f; prevB = 0.0f; }
        const float totA = __shfl_sync(0xFFFFFFFFu, wa, NW - 1);
        const float totB = __shfl_sync(0xFFFFFFFFu, wb, NW - 1);

        // ---- replay + coalesced store for this chunk ----
        float s = fmaf(Ae, fmaf(prevA, carry, prevB), Be);
        float o[4];
        #pragma unroll
        for (int k = 0; k < 4; ++k) {
            s = fmaf(av[k], s, bv[k]);
            o[k] = s;
        }
        o4[fidx] = rev ? make_float4(o[3], o[2], o[1], o[0])
                       : make_float4(o[0], o[1], o[2], o[3]);

        carry = fmaf(totA, carry, totB);   // state entering next chunk
    }
}

extern "C" void kernel_launch(void* const* d_in, const int* in_sizes, int n_in,
                              void* d_out, int out_size) {
    const float* x = (const float*)d_in[0];
    float* out = (float*)d_out;
    const int B = in_sizes[0] / (512 * L);
    cudaFuncSetAttribute(mingru_bidir_kernel,
                         cudaFuncAttributeMaxDynamicSharedMemorySize, SMEM_BYTES);
    mingru_bidir_kernel<<<B * 256, NT, SMEM_BYTES>>>(x, out);
}